// round 1
// baseline (speedup 1.0000x reference)
#include <cuda_runtime.h>
#include <cuda_bf16.h>
#include <cstdint>

#define NUM_REGIONS 116
#define NBINS 128          // padded to 128 for clean indexing
#define COPIES 4           // replicated shared histograms (by warp % 4)

__device__ float g_sums[NUM_REGIONS];
__device__ int   g_cnts[NUM_REGIONS];

// ---------------------------------------------------------------------------
// Kernel 0: zero the global accumulators (must run every launch / replay)
// ---------------------------------------------------------------------------
__global__ void zero_kernel() {
    int i = threadIdx.x;
    if (i < NUM_REGIONS) {
        g_sums[i] = 0.0f;
        g_cnts[i] = 0;
    }
}

// ---------------------------------------------------------------------------
// Kernel 1: single pass over the data. Per-region sum of |real-fake| and
// per-region element count, via replicated shared-memory histograms.
// ---------------------------------------------------------------------------
__global__ void __launch_bounds__(256, 8)
accum_kernel(const float4* __restrict__ real,
             const float4* __restrict__ fake,
             const int4*   __restrict__ rmap,
             int nvec, int ntail, int ntotal)
{
    __shared__ float s_sum[COPIES][NBINS];
    __shared__ int   s_cnt[COPIES][NBINS];

    const int tid = threadIdx.x;

    // zero shared
    #pragma unroll
    for (int i = tid; i < COPIES * NBINS; i += 256) {
        (&s_sum[0][0])[i] = 0.0f;
        (&s_cnt[0][0])[i] = 0;
    }
    __syncthreads();

    const int c = (tid >> 5) & (COPIES - 1);   // warp % 4 selects a copy
    const int stride = gridDim.x * blockDim.x;
    int i = blockIdx.x * blockDim.x + tid;

    for (; i < nvec; i += stride) {
        float4 r = real[i];
        float4 f = fake[i];
        int4   m = rmap[i];

        atomicAdd(&s_sum[c][m.x], fabsf(r.x - f.x));
        atomicAdd(&s_cnt[c][m.x], 1);
        atomicAdd(&s_sum[c][m.y], fabsf(r.y - f.y));
        atomicAdd(&s_cnt[c][m.y], 1);
        atomicAdd(&s_sum[c][m.z], fabsf(r.z - f.z));
        atomicAdd(&s_cnt[c][m.z], 1);
        atomicAdd(&s_sum[c][m.w], fabsf(r.w - f.w));
        atomicAdd(&s_cnt[c][m.w], 1);
    }

    // scalar tail (n not divisible by 4) — handled by block 0 only
    if (blockIdx.x == 0 && tid < ntail) {
        const float* realf = (const float*)real;
        const float* fakef = (const float*)fake;
        const int*   mapf  = (const int*)rmap;
        int j = ntotal - ntail + tid;
        atomicAdd(&s_sum[c][mapf[j]], fabsf(realf[j] - fakef[j]));
        atomicAdd(&s_cnt[c][mapf[j]], 1);
    }

    __syncthreads();

    // reduce the 4 copies and push to global (REDG, no return needed)
    for (int r = tid; r < NUM_REGIONS; r += 256) {
        float s = s_sum[0][r] + s_sum[1][r] + s_sum[2][r] + s_sum[3][r];
        int   n = s_cnt[0][r] + s_cnt[1][r] + s_cnt[2][r] + s_cnt[3][r];
        atomicAdd(&g_sums[r], s);
        atomicAdd(&g_cnts[r], n);
    }
}

// ---------------------------------------------------------------------------
// Kernel 2: 116-region epilogue — means, max, weights, weighted total.
// One block of 128 threads (4 warps).
// ---------------------------------------------------------------------------
__global__ void final_kernel(float* __restrict__ out, float inv_n)
{
    const int tid = threadIdx.x;   // 128 threads
    float s = 0.0f, mean = 0.0f;
    if (tid < NUM_REGIONS) {
        s = g_sums[tid];
        mean = s / ((float)g_cnts[tid] + 1e-6f);
    }

    // block-wide max of mean (means are >= 0, inactive lanes contribute 0)
    float v = mean;
    #pragma unroll
    for (int o = 16; o > 0; o >>= 1)
        v = fmaxf(v, __shfl_xor_sync(0xFFFFFFFFu, v, o));

    __shared__ float smax[4];
    __shared__ float ssum[4];
    if ((tid & 31) == 0) smax[tid >> 5] = v;
    __syncthreads();
    float maxv = fmaxf(fmaxf(smax[0], smax[1]), fmaxf(smax[2], smax[3]));
    maxv = fmaxf(maxv, 0.0f);   // jnp.maximum(max(rloss_mean), 0.0)

    // per-region weight and contribution to the weighted sum
    float w = 1.0f + 1e-3f * (mean / (maxv + 1e-6f));
    float contrib = s * w;

    #pragma unroll
    for (int o = 16; o > 0; o >>= 1)
        contrib += __shfl_xor_sync(0xFFFFFFFFu, contrib, o);
    if ((tid & 31) == 0) ssum[tid >> 5] = contrib;
    __syncthreads();

    if (tid == 0)
        out[0] = (ssum[0] + ssum[1] + ssum[2] + ssum[3]) * inv_n;
}

// ---------------------------------------------------------------------------
// Launch
// ---------------------------------------------------------------------------
extern "C" void kernel_launch(void* const* d_in, const int* in_sizes, int n_in,
                              void* d_out, int out_size)
{
    const float4* real = (const float4*)d_in[0];
    const float4* fake = (const float4*)d_in[1];
    const int4*   rmap = (const int4*)d_in[2];
    float* out = (float*)d_out;

    const int n     = in_sizes[0];       // 16*3*512*512 = 12,582,912
    const int nvec  = n >> 2;
    const int ntail = n & 3;

    int blocks = (nvec + 255) / 256;
    if (blocks > 1184) blocks = 1184;    // 8 blocks/SM * 148 SMs
    if (blocks < 1) blocks = 1;

    zero_kernel<<<1, 128>>>();
    accum_kernel<<<blocks, 256>>>(real, fake, rmap, nvec, ntail, n);
    final_kernel<<<1, 128>>>(out, 1.0f / (float)n);
}